// round 7
// baseline (speedup 1.0000x reference)
#include <cuda_runtime.h>
#include <mma.h>
#include <math.h>

using namespace nvcuda;

#define B_  128
#define C_  2048
#define HW_ 121
#define M_  (B_*HW_)   /* 15488 */

// Scratch (static device arrays — no runtime allocation).
__device__ float g_k[C_*HW_];                 // per-channel circular-conv taps [c][121]
__device__ float g_xf[31719424];              // filtered x, COL-MAJOR: element (m, c) at c*M_ + m

// ---------------------------------------------------------------------------
// K1: build real circular-conv kernel per channel.
// x_filt = Re(IFFT2(ifftshift(fftshift(FFT2(x))*Ms))) == x (circ-conv) k,
// k = IFFT2_std(Mu), Mu[u,v] = Ms[(u+5)%11,(v+5)%11]; k is real (even mask).
// ---------------------------------------------------------------------------
__global__ void build_filters(const float* __restrict__ ft) {
    __shared__ float Mu[121];
    int c = blockIdx.x;
    int t = threadIdx.x;
    float cutoff = fminf(fmaxf(ft[c], 0.05f), 0.5f);
    if (t < 121) {
        int u = t / 11, v = t % 11;
        int a = (u + 5) % 11, b = (v + 5) % 11;
        float dy = (float)(a - 5), dx = (float)(b - 5);
        float dn = sqrtf(dy*dy + dx*dx) / (sqrtf(50.0f) + 1e-6f);
        Mu[t] = 1.0f / (1.0f + expf(-10.0f * (dn - cutoff)));
    }
    __syncthreads();
    if (t < 121) {
        int h = t / 11, w = t % 11;
        float acc = 0.0f;
        for (int u = 0; u < 11; u++) {
            for (int v = 0; v < 11; v++) {
                int ph = (u*h + v*w) % 11;
                acc += Mu[u*11 + v] * cospif(2.0f * (float)ph / 11.0f);
            }
        }
        g_k[c*HW_ + t] = acc / 121.0f;
    }
}

// ---------------------------------------------------------------------------
// K2: apply the spatial filter.  Per channel: XF[b, o] = sum_i T[o,i] * X[b,i]
// (T[o,i] = k[(ho-hi)%11, (wo-wi)%11]).  One block per channel, 256 threads,
// 8x8 register tile per thread (strided: o = tx + 16*j, b = ty + 16*jb).
// Output written to g_xf in col-major [c][b*121+o] -> coalesced.
// ---------------------------------------------------------------------------
__global__ __launch_bounds__(256)
void apply_filter(const float* __restrict__ x) {
    extern __shared__ float sm[];
    float* Ts = sm;                   // 128*121 (rows 121..127 zero-padded)
    float* Xs = sm + 128*HW_;         // 128*121
    float* ks = sm + 2*128*HW_;       // 121
    int c  = blockIdx.x;
    int tx = threadIdx.x, ty = threadIdx.y;
    int tid = ty * 16 + tx;

    if (tid < HW_) ks[tid] = g_k[c*HW_ + tid];
    __syncthreads();

    for (int idx = tid; idx < 128*HW_; idx += 256) {
        int o = idx / HW_, i = idx - o*HW_;
        float v = 0.0f;
        if (o < HW_) {
            int ho = o / 11, wo = o - ho*11;
            int hi = i / 11, wi = i - hi*11;
            int dh = ho - hi; if (dh < 0) dh += 11;
            int dw = wo - wi; if (dw < 0) dw += 11;
            v = ks[dh*11 + dw];
        }
        Ts[idx] = v;
    }
    const float* xc = x + (size_t)c * HW_;
    for (int idx = tid; idx < B_*HW_; idx += 256) {
        int b = idx / HW_, i = idx - b*HW_;
        Xs[idx] = xc[(size_t)b * (C_*HW_) + i];
    }
    __syncthreads();

    float acc[8][8];
    #pragma unroll
    for (int a = 0; a < 8; a++)
        #pragma unroll
        for (int b = 0; b < 8; b++) acc[a][b] = 0.0f;

    for (int i = 0; i < HW_; i++) {
        float xr[8], tr[8];
        #pragma unroll
        for (int jb = 0; jb < 8; jb++) xr[jb] = Xs[(ty + 16*jb)*HW_ + i];
        #pragma unroll
        for (int j = 0; j < 8; j++)  tr[j]  = Ts[(tx + 16*j)*HW_ + i];
        #pragma unroll
        for (int jb = 0; jb < 8; jb++)
            #pragma unroll
            for (int j = 0; j < 8; j++)
                acc[jb][j] += xr[jb] * tr[j];
    }

    float* dst = g_xf + (size_t)c * M_;
    #pragma unroll
    for (int jb = 0; jb < 8; jb++) {
        int b = ty + 16*jb;
        #pragma unroll
        for (int j = 0; j < 8; j++) {
            int o = tx + 16*j;
            if (o < HW_) dst[b*HW_ + o] = acc[jb][j];
        }
    }
}

// ---------------------------------------------------------------------------
// K3: y = XF(15488x2048) * W^T(2048x2048) via wmma TF32, fused
// BN/ReLU/gate/residual epilogue writing out in [b][o][hw] layout.
// Block tile 128x128, Ktile 16, 8 warps (4x2) each 32x64, double-buffered.
// ---------------------------------------------------------------------------
#define LDA  132
#define LDB  20
#define ABUF (LDA*16)     /* 2112 floats */
#define BBUF (LDB*128)    /* 2560 floats */
#define NKT  (C_/16)      /* 128 */

__global__ __launch_bounds__(256)
void gemm_fused(const float* __restrict__ x,
                const float* __restrict__ Wg,
                const float* __restrict__ cb,
                const float* __restrict__ ga,
                const float* __restrict__ be,
                const float* __restrict__ me,
                const float* __restrict__ va,
                const float* __restrict__ gate,
                float* __restrict__ out) {
    extern __shared__ float sm[];
    float* As = sm;               // 2 * ABUF  (col-major m x k tile)
    float* Bs = sm + 2*ABUF;      // 2 * BBUF  (col-major k x n tile)

    int bx = blockIdx.x, by = blockIdx.y;
    int tid = threadIdx.x;
    int wid = tid >> 5;
    int wm = (wid & 3) * 32;
    int wn = (wid >> 2) * 64;

    const float* Ag = g_xf + bx * 128;                  // (m,k) at k*M_ + m
    const float* Bg = Wg + (size_t)(by * 128) * C_;     // W[n][k], k contiguous

    wmma::fragment<wmma::accumulator, 16, 16, 8, float> acc[2][4];
    #pragma unroll
    for (int mi = 0; mi < 2; mi++)
        #pragma unroll
        for (int ni = 0; ni < 4; ni++) wmma::fill_fragment(acc[mi][ni], 0.0f);

    float4 av[2], bv[2];

    auto ldg = [&](int t) {
        int k0 = t * 16;
        #pragma unroll
        for (int q = 0; q < 2; q++) {
            int idx = tid + q * 256;
            int kk = idx >> 5, mm = (idx & 31) * 4;
            av[q] = *reinterpret_cast<const float4*>(&Ag[(size_t)(k0 + kk) * M_ + mm]);
            int n = idx >> 2, kq = (idx & 3) * 4;
            bv[q] = *reinterpret_cast<const float4*>(&Bg[(size_t)n * C_ + k0 + kq]);
        }
    };
    auto sts = [&](int buf) {
        #pragma unroll
        for (int q = 0; q < 2; q++) {
            int idx = tid + q * 256;
            int kk = idx >> 5, mm = (idx & 31) * 4;
            float4 a = av[q];
            a.x = wmma::__float_to_tf32(a.x); a.y = wmma::__float_to_tf32(a.y);
            a.z = wmma::__float_to_tf32(a.z); a.w = wmma::__float_to_tf32(a.w);
            *reinterpret_cast<float4*>(&As[buf*ABUF + kk*LDA + mm]) = a;
            int n = idx >> 2, kq = (idx & 3) * 4;
            float4 b = bv[q];
            b.x = wmma::__float_to_tf32(b.x); b.y = wmma::__float_to_tf32(b.y);
            b.z = wmma::__float_to_tf32(b.z); b.w = wmma::__float_to_tf32(b.w);
            *reinterpret_cast<float4*>(&Bs[buf*BBUF + n*LDB + kq]) = b;
        }
    };
    auto comp = [&](int buf) {
        #pragma unroll
        for (int ks = 0; ks < 2; ks++) {
            wmma::fragment<wmma::matrix_a, 16, 16, 8, wmma::precision::tf32, wmma::col_major> af[2];
            wmma::fragment<wmma::matrix_b, 16, 16, 8, wmma::precision::tf32, wmma::col_major> bf[4];
            #pragma unroll
            for (int mi = 0; mi < 2; mi++)
                wmma::load_matrix_sync(af[mi], &As[buf*ABUF + (wm + mi*16) + (ks*8)*LDA], LDA);
            #pragma unroll
            for (int ni = 0; ni < 4; ni++)
                wmma::load_matrix_sync(bf[ni], &Bs[buf*BBUF + ks*8 + (wn + ni*16)*LDB], LDB);
            #pragma unroll
            for (int mi = 0; mi < 2; mi++)
                #pragma unroll
                for (int ni = 0; ni < 4; ni++)
                    wmma::mma_sync(acc[mi][ni], af[mi], bf[ni], acc[mi][ni]);
        }
    };

    ldg(0); sts(0); __syncthreads();
    int buf = 0;
    for (int t = 0; t < NKT; t++) {
        if (t + 1 < NKT) ldg(t + 1);
        comp(buf);
        __syncthreads();
        if (t + 1 < NKT) { sts(buf ^ 1); buf ^= 1; __syncthreads(); }
    }
    __syncthreads();

    // Epilogue: stash tile in smem (col-major), then BN + ReLU + gate + residual.
    float* Ep   = sm;                  // 132*128 floats, (mm,nn) at mm + nn*132
    float* s_sc = sm + 132*128;
    float* s_bi = s_sc + 128;
    #pragma unroll
    for (int mi = 0; mi < 2; mi++)
        #pragma unroll
        for (int ni = 0; ni < 4; ni++)
            wmma::store_matrix_sync(&Ep[(wm + mi*16) + (size_t)(wn + ni*16) * 132],
                                    acc[mi][ni], 132, wmma::mem_col_major);
    if (tid < 128) {
        int o = by * 128 + tid;
        float sc = ga[o] * rsqrtf(va[o] + 1e-5f);
        s_sc[tid] = sc;
        s_bi[tid] = (cb[o] - me[o]) * sc + be[o];
    }
    __syncthreads();

    float g = fminf(fmaxf(gate[0], 0.0f), 1.0f);
    #pragma unroll 4
    for (int q = 0; q < 64; q++) {
        int idx = tid + q * 256;
        int nn = idx >> 7, mm = idx & 127;
        float v = Ep[mm + nn * 132];
        v = fmaxf(v * s_sc[nn] + s_bi[nn], 0.0f);
        int m = bx * 128 + mm;
        int b = m / 121, hw = m - b * 121;
        size_t oi = (size_t)b * (C_*HW_) + (size_t)(by * 128 + nn) * HW_ + hw;
        out[oi] = x[oi] + g * v;
    }
}

// ---------------------------------------------------------------------------
extern "C" void kernel_launch(void* const* d_in, const int* in_sizes, int n_in,
                              void* d_out, int out_size) {
    const float* x    = (const float*)d_in[0];
    const float* ft   = (const float*)d_in[1];
    const float* gate = (const float*)d_in[2];
    const float* w    = (const float*)d_in[3];
    const float* cbias= (const float*)d_in[4];
    const float* ga   = (const float*)d_in[5];
    const float* be   = (const float*)d_in[6];
    const float* me   = (const float*)d_in[7];
    const float* va   = (const float*)d_in[8];
    float* out = (float*)d_out;

    build_filters<<<C_, 128>>>(ft);

    size_t smem2 = (size_t)(2*128*HW_ + 128) * sizeof(float);   // ~124.4 KB
    cudaFuncSetAttribute(apply_filter, cudaFuncAttributeMaxDynamicSharedMemorySize, (int)smem2);
    apply_filter<<<C_, dim3(16,16), smem2>>>(x);

    size_t smem3 = (size_t)(132*128 + 256) * sizeof(float);     // ~68.6 KB (>= pipeline bufs)
    cudaFuncSetAttribute(gemm_fused, cudaFuncAttributeMaxDynamicSharedMemorySize, (int)smem3);
    gemm_fused<<<dim3(121,16), 256, smem3>>>(x, w, cbias, ga, be, me, va, gate, out);
}

// round 13
// speedup vs baseline: 3.4470x; 3.4470x over previous
#include <cuda_runtime.h>
#include <cuda_bf16.h>
#include <cstdint>
#include <stdint.h>
#include <math.h>

#define B_  128
#define C_  2048
#define HW_ 121
#define M_  (B_*HW_)   /* 15488 */

// Static device scratch (no runtime allocation).
__device__ float g_k[C_*HW_];                                   // taps [c][121]
__device__ float g_xf[31719424];                                // x_filt fp32 COL-major: (m,c) at c*M_+m
__device__ __align__(1024) __nv_bfloat16 g_xfb[31719424];       // x_filt bf16 ROW-major: (m,c) at m*C_+c
__device__ __align__(1024) __nv_bfloat16 g_wb[4194304];         // W bf16 [o][c], c contiguous

// ---------------------------------------------------------------------------
// K1: per-channel circular-conv taps. cos table + incremental mod.
// ---------------------------------------------------------------------------
__global__ void build_filters(const float* __restrict__ ft) {
    __shared__ float Mu[121];
    __shared__ float ct[11];
    int c = blockIdx.x, t = threadIdx.x;
    if (t < 11) ct[t] = cospif(2.0f * (float)t / 11.0f);
    if (t < 121) {
        float cutoff = fminf(fmaxf(ft[c], 0.05f), 0.5f);
        int u = t / 11, v = t - u * 11;
        int a = (u + 5) % 11, b = (v + 5) % 11;
        float dy = (float)(a - 5), dx = (float)(b - 5);
        float dn = sqrtf(dy*dy + dx*dx) / (sqrtf(50.0f) + 1e-6f);
        Mu[t] = 1.0f / (1.0f + expf(-10.0f * (dn - cutoff)));
    }
    __syncthreads();
    if (t < 121) {
        int h = t / 11, w = t - (t / 11) * 11;
        float acc = 0.0f;
        int ru = 0;
        #pragma unroll 1
        for (int u = 0; u < 11; u++) {
            const float* mrow = &Mu[u * 11];
            int ph = ru;
            #pragma unroll
            for (int v = 0; v < 11; v++) {
                acc += mrow[v] * ct[ph];
                ph += w; if (ph >= 11) ph -= 11;
            }
            ru += h; if (ru >= 11) ru -= 11;
        }
        g_k[c*HW_ + t] = acc * (1.0f / 121.0f);
    }
}

// ---------------------------------------------------------------------------
// K2: spatial filter per channel (fp32, writes col-major g_xf).
// ---------------------------------------------------------------------------
__global__ __launch_bounds__(256)
void apply_filter(const float* __restrict__ x) {
    extern __shared__ float sm[];
    float* Ts = sm;
    float* Xs = sm + 128*HW_;
    float* ks = sm + 2*128*HW_;
    int c  = blockIdx.x;
    int tx = threadIdx.x, ty = threadIdx.y;
    int tid = ty * 16 + tx;

    if (tid < HW_) ks[tid] = g_k[c*HW_ + tid];
    __syncthreads();

    for (int idx = tid; idx < 128*HW_; idx += 256) {
        int o = idx / HW_, i = idx - o*HW_;
        float v = 0.0f;
        if (o < HW_) {
            int ho = o / 11, wo = o - ho*11;
            int hi = i / 11, wi = i - hi*11;
            int dh = ho - hi; if (dh < 0) dh += 11;
            int dw = wo - wi; if (dw < 0) dw += 11;
            v = ks[dh*11 + dw];
        }
        Ts[idx] = v;
    }
    const float* xc = x + (size_t)c * HW_;
    for (int idx = tid; idx < B_*HW_; idx += 256) {
        int b = idx / HW_, i = idx - b*HW_;
        Xs[idx] = xc[(size_t)b * (C_*HW_) + i];
    }
    __syncthreads();

    float acc[8][8];
    #pragma unroll
    for (int a = 0; a < 8; a++)
        #pragma unroll
        for (int b = 0; b < 8; b++) acc[a][b] = 0.0f;

    for (int i = 0; i < HW_; i++) {
        float xr[8], tr[8];
        #pragma unroll
        for (int jb = 0; jb < 8; jb++) xr[jb] = Xs[(ty + 16*jb)*HW_ + i];
        #pragma unroll
        for (int j = 0; j < 8; j++)  tr[j]  = Ts[(tx + 16*j)*HW_ + i];
        #pragma unroll
        for (int jb = 0; jb < 8; jb++)
            #pragma unroll
            for (int j = 0; j < 8; j++)
                acc[jb][j] += xr[jb] * tr[j];
    }

    float* dst = g_xf + (size_t)c * M_;
    #pragma unroll
    for (int jb = 0; jb < 8; jb++) {
        int b = ty + 16*jb;
        #pragma unroll
        for (int j = 0; j < 8; j++) {
            int o = tx + 16*j;
            if (o < HW_) dst[b*HW_ + o] = acc[jb][j];
        }
    }
}

// ---------------------------------------------------------------------------
// K2b: transpose + fp32->bf16 convert: g_xf [c][m] -> g_xfb [m][c].
// ---------------------------------------------------------------------------
__global__ __launch_bounds__(256)
void transpose_bf16() {
    __shared__ float tile[32][33];
    int m0 = blockIdx.x * 32, c0 = blockIdx.y * 32;
    int tx = threadIdx.x, ty = threadIdx.y;   // 32 x 8
    #pragma unroll
    for (int r = 0; r < 32; r += 8)
        tile[ty + r][tx] = g_xf[(size_t)(c0 + ty + r) * M_ + m0 + tx];
    __syncthreads();
    #pragma unroll
    for (int r = 0; r < 32; r += 8)
        g_xfb[(size_t)(m0 + ty + r) * C_ + c0 + tx] = __float2bfloat16_rn(tile[tx][ty + r]);
}

// K2c: W fp32 -> bf16 (layout preserved, k contiguous).
__global__ __launch_bounds__(256)
void convert_w(const float4* __restrict__ w) {
    int i = blockIdx.x * 256 + threadIdx.x;
    float4 v = w[i];
    __nv_bfloat162* d2 = reinterpret_cast<__nv_bfloat162*>(g_wb);
    d2[2*i]   = __floats2bfloat162_rn(v.x, v.y);
    d2[2*i+1] = __floats2bfloat162_rn(v.z, v.w);
}

// ---------------------------------------------------------------------------
// K3: bf16 mma.sync (HMMA) GEMM, CTA tile 128x128, K-tile 64, cp.async double
// buffer, SW128-swizzled smem + ldmatrix. D[m,n] = sum_k XFB[m,k]*WB[n,k].
// Fused BN/ReLU/gate/residual epilogue staged through smem for coalescing.
// ---------------------------------------------------------------------------
#define KT_    64
#define NKT_   (C_/KT_)          /* 32 */
#define ASTG   16384             /* 128 rows x 128B */
#define BSTG   16384             /* 128 rows x 128B */
#define SW(o)  ((o) ^ (((o) >> 3) & 0x70))

__device__ __forceinline__ uint32_t smem_addr_u32(const void* p) {
    uint32_t a;
    asm("{ .reg .u64 t; cvta.to.shared.u64 t, %1; cvt.u32.u64 %0, t; }" : "=r"(a) : "l"(p));
    return a;
}
__device__ __forceinline__ void cpa16(uint32_t s, const void* g) {
    asm volatile("cp.async.cg.shared.global [%0], [%1], 16;" :: "r"(s), "l"(g));
}
__device__ __forceinline__ void ldsm4(uint32_t* r, uint32_t addr) {
    asm volatile("ldmatrix.sync.aligned.m8n8.x4.shared.b16 {%0,%1,%2,%3}, [%4];"
                 : "=r"(r[0]), "=r"(r[1]), "=r"(r[2]), "=r"(r[3]) : "r"(addr));
}
__device__ __forceinline__ void mma16816(float* d, const uint32_t* a, uint32_t b0, uint32_t b1) {
    asm volatile(
        "mma.sync.aligned.m16n8k16.row.col.f32.bf16.bf16.f32 "
        "{%0,%1,%2,%3}, {%4,%5,%6,%7}, {%8,%9}, {%0,%1,%2,%3};"
        : "+f"(d[0]), "+f"(d[1]), "+f"(d[2]), "+f"(d[3])
        : "r"(a[0]), "r"(a[1]), "r"(a[2]), "r"(a[3]), "r"(b0), "r"(b1));
}

__global__ __launch_bounds__(256, 2)
void gemm_tc(const float* __restrict__ x,
             const float* __restrict__ cb, const float* __restrict__ ga,
             const float* __restrict__ be, const float* __restrict__ me,
             const float* __restrict__ va, const float* __restrict__ gate,
             float* __restrict__ out) {
    extern __shared__ char smc[];
    uint32_t sb    = smem_addr_u32(smc);
    uint32_t tiles = (sb + 1023) & ~1023u;          // 1024-aligned
    uint32_t A0 = tiles;                            // 2 A stages
    uint32_t B0 = tiles + 2*ASTG;                   // 2 B stages

    int tid = threadIdx.x, wid = tid >> 5, lane = tid & 31;
    int bx = blockIdx.x, by = blockIdx.y;
    int wm = (wid & 1) * 64;                        // warp tile 64(m) x 32(n)
    int wn = (wid >> 1) * 32;

    const __nv_bfloat16* Ag = g_xfb + (size_t)(bx * 128) * C_;
    const __nv_bfloat16* Bg = g_wb  + (size_t)(by * 128) * C_;

    auto load_stage = [&](int kt, int buf) {
        const __nv_bfloat16* as = Ag + kt * KT_;
        const __nv_bfloat16* bs = Bg + kt * KT_;
        uint32_t Ab = A0 + buf * ASTG, Bb = B0 + buf * BSTG;
        #pragma unroll
        for (int q = 0; q < 4; q++) {               // A: 128 rows x 8 chunks of 16B
            int idx = tid + q * 256;
            int row = idx >> 3, ch = idx & 7;
            uint32_t off = row * 128 + ch * 16;
            cpa16(Ab + SW(off), as + (size_t)row * C_ + ch * 8);
        }
        #pragma unroll
        for (int q = 0; q < 4; q++) {               // B: 128 rows x 8 chunks of 16B
            int idx = tid + q * 256;
            int row = idx >> 3, ch = idx & 7;
            uint32_t off = row * 128 + ch * 16;
            cpa16(Bb + SW(off), bs + (size_t)row * C_ + ch * 8);
        }
    };

    float acc[4][4][4];
    #pragma unroll
    for (int mi = 0; mi < 4; mi++)
        #pragma unroll
        for (int ni = 0; ni < 4; ni++)
            #pragma unroll
            for (int e = 0; e < 4; e++) acc[mi][ni][e] = 0.0f;

    // ldmatrix per-lane address components (element (row, k) at byte row*128+k*2).
    int a_row  = wm + ((lane >> 3) & 1) * 8 + (lane & 7);   // +mi*16
    int a_colb = (lane >> 4) * 16;                          // +ks*32
    int b_row  = wn + ((lane >> 4) << 3) + (lane & 7);      // +np*16
    int b_colb = ((lane >> 3) & 1) * 16;                    // +ks*32

    load_stage(0, 0);
    asm volatile("cp.async.commit_group;" ::: "memory");
    load_stage(1, 1);
    asm volatile("cp.async.commit_group;" ::: "memory");

    #pragma unroll 1
    for (int t = 0; t < NKT_; t++) {
        int buf = t & 1;
        asm volatile("cp.async.wait_group 1;" ::: "memory");   // stage t landed
        __syncthreads();

        uint32_t Ab = A0 + buf * ASTG, Bb = B0 + buf * BSTG;
        #pragma unroll
        for (int ks = 0; ks < 4; ks++) {
            uint32_t af[4][4], bf[2][4];
            #pragma unroll
            for (int mi = 0; mi < 4; mi++) {
                uint32_t off = (uint32_t)(a_row + mi*16) * 128 + ks*32 + a_colb;
                ldsm4(af[mi], Ab + SW(off));
            }
            #pragma unroll
            for (int np = 0; np < 2; np++) {
                uint32_t off = (uint32_t)(b_row + np*16) * 128 + ks*32 + b_colb;
                ldsm4(bf[np], Bb + SW(off));
            }
            #pragma unroll
            for (int mi = 0; mi < 4; mi++)
                #pragma unroll
                for (int ni = 0; ni < 4; ni++)
                    mma16816(acc[mi][ni], af[mi],
                             bf[ni >> 1][(ni & 1) * 2], bf[ni >> 1][(ni & 1) * 2 + 1]);
        }
        __syncthreads();                                        // reads done before refill
        if (t + 2 < NKT_) {
            load_stage(t + 2, buf);
            asm volatile("cp.async.commit_group;" ::: "memory");
        } else {
            asm volatile("cp.async.commit_group;" ::: "memory"); // keep group count in step
        }
    }

    // Epilogue: stash tile in smem col-major (pitch 132), then BN+ReLU+gate+res.
    float* Ep   = reinterpret_cast<float*>(smc + (tiles - sb));
    float* s_sc = Ep + 132 * 128;
    float* s_bi = s_sc + 128;
    __syncthreads();
    {
        int r0 = lane >> 2, c0 = (lane & 3) * 2;
        #pragma unroll
        for (int mi = 0; mi < 4; mi++) {
            int mrow = wm + mi * 16 + r0;
            #pragma unroll
            for (int ni = 0; ni < 4; ni++) {
                int ncol = wn + ni * 8 + c0;
                Ep[(mrow)     + (ncol)     * 132] = acc[mi][ni][0];
                Ep[(mrow)     + (ncol + 1) * 132] = acc[mi][ni][1];
                Ep[(mrow + 8) + (ncol)     * 132] = acc[mi][ni][2];
                Ep[(mrow + 8) + (ncol + 1) * 132] = acc[mi][ni][3];
            }
        }
    }
    if (tid < 128) {
        int o = by * 128 + tid;
        float sc = ga[o] * rsqrtf(va[o] + 1e-5f);
        s_sc[tid] = sc;
        s_bi[tid] = (cb[o] - me[o]) * sc + be[o];
    }
    __syncthreads();

    float g = fminf(fmaxf(gate[0], 0.0f), 1.0f);
    #pragma unroll 4
    for (int q = 0; q < 64; q++) {
        int idx = tid + q * 256;
        int nn = idx >> 7, mm = idx & 127;
        float v = Ep[mm + nn * 132];
        v = fmaxf(v * s_sc[nn] + s_bi[nn], 0.0f);
        int m = bx * 128 + mm;
        int b = m / 121, hw = m - b * 121;
        size_t oi = (size_t)b * (C_*HW_) + (size_t)(by * 128 + nn) * HW_ + hw;
        out[oi] = x[oi] + g * v;
    }
}

// ---------------------------------------------------------------------------
extern "C" void kernel_launch(void* const* d_in, const int* in_sizes, int n_in,
                              void* d_out, int out_size) {
    const float* x    = (const float*)d_in[0];
    const float* ft   = (const float*)d_in[1];
    const float* gate = (const float*)d_in[2];
    const float* w    = (const float*)d_in[3];
    const float* cbias= (const float*)d_in[4];
    const float* ga   = (const float*)d_in[5];
    const float* be   = (const float*)d_in[6];
    const float* me   = (const float*)d_in[7];
    const float* va   = (const float*)d_in[8];
    float* out = (float*)d_out;

    build_filters<<<C_, 128>>>(ft);

    size_t smem2 = (size_t)(2*128*HW_ + 128) * sizeof(float);   // ~124.4 KB
    cudaFuncSetAttribute(apply_filter, cudaFuncAttributeMaxDynamicSharedMemorySize, (int)smem2);
    apply_filter<<<C_, dim3(16,16), smem2>>>(x);

    transpose_bf16<<<dim3(M_/32, C_/32), dim3(32,8)>>>();
    convert_w<<<(C_*C_/4)/256, 256>>>((const float4*)w);

    // dynamic smem: max(align pad + 2 A stages + 2 B stages, epilogue tile+params)
    size_t stages = 1024 + 2*ASTG + 2*BSTG;                     // 66.6 KB
    size_t epi    = 1024 + (132*128 + 256) * sizeof(float);     // ~69.6 KB
    size_t smem3  = stages > epi ? stages : epi;
    cudaFuncSetAttribute(gemm_tc, cudaFuncAttributeMaxDynamicSharedMemorySize, (int)smem3);
    gemm_tc<<<dim3(121, 16), 256, smem3>>>(x, cbias, ga, be, me, va, gate, out);
}

// round 15
// speedup vs baseline: 6.6692x; 1.9348x over previous
#include <cuda_runtime.h>
#include <cuda_bf16.h>
#include <cstdint>
#include <stdint.h>
#include <math.h>

#define B_  128
#define C_  2048
#define HW_ 121
#define M_  (B_*HW_)   /* 15488 */

// Static device scratch (no runtime allocation).
// x_filt bf16 COL-major: element (m, c) at c*M_ + m  (i.e. [c][m], m contiguous)
__device__ __align__(1024) __nv_bfloat16 g_xfb[31719424];
__device__ __align__(1024) __nv_bfloat16 g_wb[4194304];   // W bf16 [o][c], c contiguous

__device__ __forceinline__ uint32_t smem_addr_u32(const void* p) {
    uint32_t a;
    asm("{ .reg .u64 t; cvta.to.shared.u64 t, %1; cvt.u32.u64 %0, t; }" : "=r"(a) : "l"(p));
    return a;
}
__device__ __forceinline__ void cpa16(uint32_t s, const void* g) {
    asm volatile("cp.async.cg.shared.global [%0], [%1], 16;" :: "r"(s), "l"(g));
}
__device__ __forceinline__ void ldsm4(uint32_t* r, uint32_t addr) {
    asm volatile("ldmatrix.sync.aligned.m8n8.x4.shared.b16 {%0,%1,%2,%3}, [%4];"
                 : "=r"(r[0]), "=r"(r[1]), "=r"(r[2]), "=r"(r[3]) : "r"(addr));
}
__device__ __forceinline__ void ldsm4t(uint32_t* r, uint32_t addr) {
    asm volatile("ldmatrix.sync.aligned.m8n8.x4.trans.shared.b16 {%0,%1,%2,%3}, [%4];"
                 : "=r"(r[0]), "=r"(r[1]), "=r"(r[2]), "=r"(r[3]) : "r"(addr));
}
__device__ __forceinline__ void mma16816(float* d, const uint32_t* a, uint32_t b0, uint32_t b1) {
    asm volatile(
        "mma.sync.aligned.m16n8k16.row.col.f32.bf16.bf16.f32 "
        "{%0,%1,%2,%3}, {%4,%5,%6,%7}, {%8,%9}, {%0,%1,%2,%3};"
        : "+f"(d[0]), "+f"(d[1]), "+f"(d[2]), "+f"(d[3])
        : "r"(a[0]), "r"(a[1]), "r"(a[2]), "r"(a[3]), "r"(b0), "r"(b1));
}

// ---------------------------------------------------------------------------
// K2': fused taps + spatial filter via bf16 mma, one block per channel.
//   XF[b,o] = sum_i T_c[o,i] * X[b,i];  T_c[o,i] = k_c[(ho-hi)%11, (wo-wi)%11]
// A = X (row-major b x i), B = T (n=o, k=i, k-contiguous). Both padded to 128.
// Output written bf16 col-major: g_xfb[c*M_ + b*121 + o]  (coalesced).
// Smem rows are 256B; swizzle: chunk16 ^= (row & 7).
// Header region is 2048B (ct 64B + Mu 512B + ks 512B = 1088B) — tile region
// MUST start past it (R14 bug: 1024B header aliased ks[112..120] with T row 0).
// ---------------------------------------------------------------------------
__global__ __launch_bounds__(256)
void filter_mma2(const float* __restrict__ x, const float* __restrict__ ft) {
    extern __shared__ char smf[];
    float* ct = reinterpret_cast<float*>(smf);        // 16 (11 used)
    float* Mu = ct + 16;                              // 128 (121 used)
    float* ks = Mu + 128;                             // 128 (121 used)
    char*  base = smf + 2048;                         // T: 32KB, X: 32KB
    uint32_t sb = smem_addr_u32(base);
    uint32_t Tb = sb, Xb = sb + 32768;

    int c = blockIdx.x;
    int tid = threadIdx.x, wid = tid >> 5, lane = tid & 31;

    if (tid < 11) ct[tid] = cospif(2.0f * (float)tid / 11.0f);
    if (tid < 121) {
        float cutoff = fminf(fmaxf(ft[c], 0.05f), 0.5f);
        int u = tid / 11, v = tid - u * 11;
        int a = (u + 5) % 11, b = (v + 5) % 11;
        float dy = (float)(a - 5), dx = (float)(b - 5);
        float dn = sqrtf(dy*dy + dx*dx) / (sqrtf(50.0f) + 1e-6f);
        Mu[tid] = 1.0f / (1.0f + expf(-10.0f * (dn - cutoff)));
    }
    __syncthreads();
    if (tid < 121) {
        int h = tid / 11, w = tid - (tid / 11) * 11;
        float acc = 0.0f;
        int ru = 0;
        #pragma unroll 1
        for (int u = 0; u < 11; u++) {
            const float* mrow = &Mu[u * 11];
            int ph = ru;
            #pragma unroll
            for (int v = 0; v < 11; v++) {
                acc += mrow[v] * ct[ph];
                ph += w; if (ph >= 11) ph -= 11;
            }
            ru += h; if (ru >= 11) ru -= 11;
        }
        ks[tid] = acc * (1.0f / 121.0f);
    }
    __syncthreads();

    // --- build T (o rows x i cols, bf16, swizzled 256B rows) ---
    for (int idx = tid; idx < 16384; idx += 256) {
        int o = idx >> 7, i = idx & 127;
        float v = 0.0f;
        if (o < 121 && i < 121) {
            int ho = o / 11, wo = o - ho*11;
            int hi = i / 11, wi = i - hi*11;
            int dh = ho - hi; if (dh < 0) dh += 11;
            int dw = wo - wi; if (dw < 0) dw += 11;
            v = ks[dh*11 + dw];
        }
        uint32_t off = (uint32_t)o*256 + ((((uint32_t)i >> 3) ^ (o & 7)) << 4) + (i & 7)*2;
        *reinterpret_cast<__nv_bfloat16*>(base + off) = __float2bfloat16_rn(v);
    }
    // --- load X (b rows x i cols) ---
    const float* xc = x + (size_t)c * HW_;
    for (int idx = tid; idx < 16384; idx += 256) {
        int b = idx >> 7, i = idx & 127;
        float v = (i < 121) ? xc[(size_t)b * (C_*HW_) + i] : 0.0f;
        uint32_t off = 32768u + (uint32_t)b*256 + ((((uint32_t)i >> 3) ^ (b & 7)) << 4) + (i & 7)*2;
        *reinterpret_cast<__nv_bfloat16*>(base + off) = __float2bfloat16_rn(v);
    }
    __syncthreads();

    // --- mma: warp tile 64(m=b) x 32(n=o); 8 k-steps of 16 ---
    int wm = (wid & 1) * 64, wn = (wid >> 1) * 32;
    float acc[4][4][4];
    #pragma unroll
    for (int mi = 0; mi < 4; mi++)
        #pragma unroll
        for (int ni = 0; ni < 4; ni++)
            #pragma unroll
            for (int e = 0; e < 4; e++) acc[mi][ni][e] = 0.0f;

    int a_row = ((lane >> 3) & 1) * 8 + (lane & 7);   // + wm + mi*16
    int a_kc  = (lane >> 4);                          // + k2*2
    int b_row = ((lane >> 4) << 3) + (lane & 7);      // + wn + np*16
    int b_kc  = ((lane >> 3) & 1);                    // + k2*2

    #pragma unroll 1
    for (int k2 = 0; k2 < 8; k2++) {
        uint32_t af[4][4], bf[2][4];
        #pragma unroll
        for (int mi = 0; mi < 4; mi++) {
            int row = wm + mi*16 + a_row;
            uint32_t addr = Xb + (uint32_t)row*256 + (((uint32_t)(k2*2 + a_kc) ^ (row & 7)) << 4);
            ldsm4(af[mi], addr);
        }
        #pragma unroll
        for (int np = 0; np < 2; np++) {
            int row = wn + np*16 + b_row;
            uint32_t addr = Tb + (uint32_t)row*256 + (((uint32_t)(k2*2 + b_kc) ^ (row & 7)) << 4);
            ldsm4(bf[np], addr);
        }
        #pragma unroll
        for (int mi = 0; mi < 4; mi++)
            #pragma unroll
            for (int ni = 0; ni < 4; ni++)
                mma16816(acc[mi][ni], af[mi],
                         bf[ni >> 1][(ni & 1) * 2], bf[ni >> 1][(ni & 1) * 2 + 1]);
    }
    __syncthreads();

    // --- stage D as bf16, pitch 264B (bank-spread), then coalesced copy-out ---
    {
        int r0 = lane >> 2, c0 = (lane & 3) * 2;
        #pragma unroll
        for (int mi = 0; mi < 4; mi++) {
            int brow = wm + mi*16 + r0;
            #pragma unroll
            for (int ni = 0; ni < 4; ni++) {
                int ocol = wn + ni*8 + c0;
                *reinterpret_cast<__nv_bfloat162*>(base + (size_t)brow*264 + ocol*2) =
                    __floats2bfloat162_rn(acc[mi][ni][0], acc[mi][ni][1]);
                *reinterpret_cast<__nv_bfloat162*>(base + (size_t)(brow+8)*264 + ocol*2) =
                    __floats2bfloat162_rn(acc[mi][ni][2], acc[mi][ni][3]);
            }
        }
    }
    __syncthreads();
    __nv_bfloat16* dst = g_xfb + (size_t)c * M_;
    for (int idx = tid; idx < M_; idx += 256) {
        int b = idx / 121, o = idx - b * 121;
        dst[idx] = *reinterpret_cast<__nv_bfloat16*>(base + (size_t)b*264 + o*2);
    }
}

// K2c: W fp32 -> bf16 (layout preserved, k contiguous).
__global__ __launch_bounds__(256)
void convert_w(const float4* __restrict__ w) {
    int i = blockIdx.x * 256 + threadIdx.x;
    float4 v = w[i];
    __nv_bfloat162* d2 = reinterpret_cast<__nv_bfloat162*>(g_wb);
    d2[2*i]   = __floats2bfloat162_rn(v.x, v.y);
    d2[2*i+1] = __floats2bfloat162_rn(v.z, v.w);
}

// ---------------------------------------------------------------------------
// K3: bf16 mma.sync GEMM. A = x_filt, COL-major [k][m] in gmem, staged into
// 256B-row swizzled smem, consumed via ldmatrix.trans. B = W row-major [n][k],
// 128B-row SW128. CTA 128x128, K-tile 64, cp.async double buffer.
// Fused BN/ReLU/gate/residual epilogue.
// ---------------------------------------------------------------------------
#define KT_    64
#define NKT_   (C_/KT_)          /* 32 */
#define ASTG   16384             /* 64 k-rows x 256B */
#define BSTG   16384             /* 128 n-rows x 128B */
#define SW(o)  ((o) ^ (((o) >> 3) & 0x70))

__global__ __launch_bounds__(256, 2)
void gemm_tc(const float* __restrict__ x,
             const float* __restrict__ cb, const float* __restrict__ ga,
             const float* __restrict__ be, const float* __restrict__ me,
             const float* __restrict__ va, const float* __restrict__ gate,
             float* __restrict__ out) {
    extern __shared__ char smc[];
    uint32_t sb    = smem_addr_u32(smc);
    uint32_t tiles = (sb + 1023) & ~1023u;
    uint32_t A0 = tiles;
    uint32_t B0 = tiles + 2*ASTG;

    int tid = threadIdx.x, wid = tid >> 5, lane = tid & 31;
    int bx = blockIdx.x, by = blockIdx.y;
    int wm = (wid & 1) * 64;
    int wn = (wid >> 1) * 32;

    const __nv_bfloat16* Ag = g_xfb + bx * 128;          // (k,m) at k*M_ + m
    const __nv_bfloat16* Bg = g_wb  + (size_t)(by * 128) * C_;

    auto load_stage = [&](int kt, int buf) {
        const __nv_bfloat16* as = Ag + (size_t)(kt * KT_) * M_;
        const __nv_bfloat16* bs = Bg + kt * KT_;
        uint32_t Ab = A0 + buf * ASTG, Bb = B0 + buf * BSTG;
        #pragma unroll
        for (int q = 0; q < 4; q++) {               // A: 64 k-rows x 16 chunks of 16B
            int idx = tid + q * 256;
            int row = idx >> 4, ch = idx & 15;
            cpa16(Ab + (uint32_t)row*256 + (((uint32_t)ch ^ (row & 7)) << 4),
                  as + (size_t)row * M_ + ch * 8);
        }
        #pragma unroll
        for (int q = 0; q < 4; q++) {               // B: 128 n-rows x 8 chunks of 16B
            int idx = tid + q * 256;
            int row = idx >> 3, ch = idx & 7;
            uint32_t off = row * 128 + ch * 16;
            cpa16(Bb + SW(off), bs + (size_t)row * C_ + ch * 8);
        }
    };

    float acc[4][4][4];
    #pragma unroll
    for (int mi = 0; mi < 4; mi++)
        #pragma unroll
        for (int ni = 0; ni < 4; ni++)
            #pragma unroll
            for (int e = 0; e < 4; e++) acc[mi][ni][e] = 0.0f;

    // A (trans): slot s=lane>>3: m_half=s&1, k_half=s>>1.
    int at_k  = ((lane >> 4) & 1) * 8 + (lane & 7);   // + ks*16  (k-row)
    int at_mh = ((lane >> 3) & 1) * 8;                // + wm + mi*16 (m elems)
    // B (non-trans), 128B rows:
    int b_row  = wn + ((lane >> 4) << 3) + (lane & 7);
    int b_colb = ((lane >> 3) & 1) * 16;

    load_stage(0, 0);
    asm volatile("cp.async.commit_group;" ::: "memory");
    load_stage(1, 1);
    asm volatile("cp.async.commit_group;" ::: "memory");

    #pragma unroll 1
    for (int t = 0; t < NKT_; t++) {
        int buf = t & 1;
        asm volatile("cp.async.wait_group 1;" ::: "memory");
        __syncthreads();

        uint32_t Ab = A0 + buf * ASTG, Bb = B0 + buf * BSTG;
        #pragma unroll
        for (int ks = 0; ks < 4; ks++) {
            uint32_t af[4][4], bf[2][4];
            int krow = ks * 16 + at_k;
            #pragma unroll
            for (int mi = 0; mi < 4; mi++) {
                int me = wm + mi*16 + at_mh;
                uint32_t addr = Ab + (uint32_t)krow*256 + ((((uint32_t)me >> 3) ^ (krow & 7)) << 4);
                ldsm4t(af[mi], addr);
            }
            #pragma unroll
            for (int np = 0; np < 2; np++) {
                uint32_t off = (uint32_t)(b_row + np*16) * 128 + ks*32 + b_colb;
                ldsm4(bf[np], Bb + SW(off));
            }
            #pragma unroll
            for (int mi = 0; mi < 4; mi++)
                #pragma unroll
                for (int ni = 0; ni < 4; ni++)
                    mma16816(acc[mi][ni], af[mi],
                             bf[ni >> 1][(ni & 1) * 2], bf[ni >> 1][(ni & 1) * 2 + 1]);
        }
        __syncthreads();
        if (t + 2 < NKT_) {
            load_stage(t + 2, buf);
            asm volatile("cp.async.commit_group;" ::: "memory");
        } else {
            asm volatile("cp.async.commit_group;" ::: "memory");
        }
    }

    // Epilogue: smem col-major (pitch 132) + BN/ReLU/gate/residual.
    float* Ep   = reinterpret_cast<float*>(smc + (tiles - sb));
    float* s_sc = Ep + 132 * 128;
    float* s_bi = s_sc + 128;
    __syncthreads();
    {
        int r0 = lane >> 2, c0 = (lane & 3) * 2;
        #pragma unroll
        for (int mi = 0; mi < 4; mi++) {
            int mrow = wm + mi * 16 + r0;
            #pragma unroll
            for (int ni = 0; ni < 4; ni++) {
                int ncol = wn + ni * 8 + c0;
                Ep[(mrow)     + (ncol)     * 132] = acc[mi][ni][0];
                Ep[(mrow)     + (ncol + 1) * 132] = acc[mi][ni][1];
                Ep[(mrow + 8) + (ncol)     * 132] = acc[mi][ni][2];
                Ep[(mrow + 8) + (ncol + 1) * 132] = acc[mi][ni][3];
            }
        }
    }
    if (tid < 128) {
        int o = by * 128 + tid;
        float sc = ga[o] * rsqrtf(va[o] + 1e-5f);
        s_sc[tid] = sc;
        s_bi[tid] = (cb[o] - me[o]) * sc + be[o];
    }
    __syncthreads();

    float g = fminf(fmaxf(gate[0], 0.0f), 1.0f);
    #pragma unroll 4
    for (int q = 0; q < 64; q++) {
        int idx = tid + q * 256;
        int nn = idx >> 7, mm = idx & 127;
        float v = Ep[mm + nn * 132];
        v = fmaxf(v * s_sc[nn] + s_bi[nn], 0.0f);
        int m = bx * 128 + mm;
        int b = m / 121, hw = m - b * 121;
        size_t oi = (size_t)b * (C_*HW_) + (size_t)(by * 128 + nn) * HW_ + hw;
        out[oi] = x[oi] + g * v;
    }
}

// ---------------------------------------------------------------------------
extern "C" void kernel_launch(void* const* d_in, const int* in_sizes, int n_in,
                              void* d_out, int out_size) {
    const float* x    = (const float*)d_in[0];
    const float* ft   = (const float*)d_in[1];
    const float* gate = (const float*)d_in[2];
    const float* w    = (const float*)d_in[3];
    const float* cbias= (const float*)d_in[4];
    const float* ga   = (const float*)d_in[5];
    const float* be   = (const float*)d_in[6];
    const float* me   = (const float*)d_in[7];
    const float* va   = (const float*)d_in[8];
    float* out = (float*)d_out;

    size_t smemF = 2048 + 2 * 32768;                 // hdr + T + X
    cudaFuncSetAttribute(filter_mma2, cudaFuncAttributeMaxDynamicSharedMemorySize, (int)smemF);
    filter_mma2<<<C_, 256, smemF>>>(x, ft);

    convert_w<<<(C_*C_/4)/256, 256>>>((const float4*)w);

    size_t stages = 1024 + 2*ASTG + 2*BSTG;          // 66.6 KB
    size_t epi    = 1024 + (132*128 + 256) * sizeof(float);
    size_t smem3  = stages > epi ? stages : epi;
    cudaFuncSetAttribute(gemm_tc, cudaFuncAttributeMaxDynamicSharedMemorySize, (int)smem3);
    gemm_tc<<<dim3(121, 16), 256, smem3>>>(x, cbias, ga, be, me, va, gate, out);
}

// round 16
// speedup vs baseline: 6.8457x; 1.0265x over previous
#include <cuda_runtime.h>
#include <cuda_bf16.h>
#include <cstdint>
#include <stdint.h>
#include <math.h>

#define B_  128
#define C_  2048
#define HW_ 121
#define M_  (B_*HW_)   /* 15488 */

// Static device scratch (no runtime allocation).
// x_filt bf16 COL-major: element (m, c) at c*M_ + m  (i.e. [c][m], m contiguous)
__device__ __align__(1024) __nv_bfloat16 g_xfb[31719424];
__device__ __align__(1024) __nv_bfloat16 g_wb[4194304];   // W bf16 [o][c], c contiguous

__device__ __forceinline__ uint32_t smem_addr_u32(const void* p) {
    uint32_t a;
    asm("{ .reg .u64 t; cvta.to.shared.u64 t, %1; cvt.u32.u64 %0, t; }" : "=r"(a) : "l"(p));
    return a;
}
__device__ __forceinline__ void cpa16(uint32_t s, const void* g) {
    asm volatile("cp.async.cg.shared.global [%0], [%1], 16;" :: "r"(s), "l"(g));
}
__device__ __forceinline__ void ldsm4(uint32_t* r, uint32_t addr) {
    asm volatile("ldmatrix.sync.aligned.m8n8.x4.shared.b16 {%0,%1,%2,%3}, [%4];"
                 : "=r"(r[0]), "=r"(r[1]), "=r"(r[2]), "=r"(r[3]) : "r"(addr));
}
__device__ __forceinline__ void ldsm4t(uint32_t* r, uint32_t addr) {
    asm volatile("ldmatrix.sync.aligned.m8n8.x4.trans.shared.b16 {%0,%1,%2,%3}, [%4];"
                 : "=r"(r[0]), "=r"(r[1]), "=r"(r[2]), "=r"(r[3]) : "r"(addr));
}
__device__ __forceinline__ void mma16816(float* d, const uint32_t* a, uint32_t b0, uint32_t b1) {
    asm volatile(
        "mma.sync.aligned.m16n8k16.row.col.f32.bf16.bf16.f32 "
        "{%0,%1,%2,%3}, {%4,%5,%6,%7}, {%8,%9}, {%0,%1,%2,%3};"
        : "+f"(d[0]), "+f"(d[1]), "+f"(d[2]), "+f"(d[3])
        : "r"(a[0]), "r"(a[1]), "r"(a[2]), "r"(a[3]), "r"(b0), "r"(b1));
}

// ---------------------------------------------------------------------------
// K2': fused taps + spatial filter via bf16 mma, one block per channel.
// Warp-specialized: warps 0-3 stream X (gmem->smem bf16) while warps 4-7
// compute Mu -> taps -> T tile. Sub-block phases use bar.sync 1,128.
// Header region 2048B (ct 64B + Mu 512B + ks 512B) — tiles start at +2048.
// ---------------------------------------------------------------------------
__global__ __launch_bounds__(256, 3)
void filter_mma2(const float* __restrict__ x, const float* __restrict__ ft) {
    extern __shared__ char smf[];
    float* ct = reinterpret_cast<float*>(smf);        // 16 (11 used)
    float* Mu = ct + 16;                              // 128 (121 used)
    float* ks = Mu + 128;                             // 128 (121 used)
    char*  base = smf + 2048;                         // T: 32KB, X: 32KB
    uint32_t sb = smem_addr_u32(base);
    uint32_t Tb = sb, Xb = sb + 32768;

    int c = blockIdx.x;
    int tid = threadIdx.x, wid = tid >> 5, lane = tid & 31;

    if (wid >= 4) {
        // --- consumer half: taps + T tile ---
        int wg = tid - 128;
        if (wg < 11) ct[wg] = cospif(2.0f * (float)wg / 11.0f);
        if (wg < 121) {
            float cutoff = fminf(fmaxf(ft[c], 0.05f), 0.5f);
            int u = wg / 11, v = wg - u * 11;
            int a = (u + 5) % 11, b = (v + 5) % 11;
            float dy = (float)(a - 5), dx = (float)(b - 5);
            float dn = sqrtf(dy*dy + dx*dx) / (sqrtf(50.0f) + 1e-6f);
            Mu[wg] = 1.0f / (1.0f + expf(-10.0f * (dn - cutoff)));
        }
        asm volatile("bar.sync 1, 128;" ::: "memory");
        if (wg < 121) {
            int h = wg / 11, w = wg - (wg / 11) * 11;
            float acc = 0.0f;
            int ru = 0;
            #pragma unroll 1
            for (int u = 0; u < 11; u++) {
                const float* mrow = &Mu[u * 11];
                int ph = ru;
                #pragma unroll
                for (int v = 0; v < 11; v++) {
                    acc += mrow[v] * ct[ph];
                    ph += w; if (ph >= 11) ph -= 11;
                }
                ru += h; if (ru >= 11) ru -= 11;
            }
            ks[wg] = acc * (1.0f / 121.0f);
        }
        asm volatile("bar.sync 1, 128;" ::: "memory");
        // build T (o rows x i cols, bf16, swizzled 256B rows)
        for (int idx = wg; idx < 16384; idx += 128) {
            int o = idx >> 7, i = idx & 127;
            float v = 0.0f;
            if (o < 121 && i < 121) {
                int ho = o / 11, wo = o - ho*11;
                int hi = i / 11, wi = i - hi*11;
                int dh = ho - hi; if (dh < 0) dh += 11;
                int dw = wo - wi; if (dw < 0) dw += 11;
                v = ks[dh*11 + dw];
            }
            uint32_t off = (uint32_t)o*256 + ((((uint32_t)i >> 3) ^ (o & 7)) << 4) + (i & 7)*2;
            *reinterpret_cast<__nv_bfloat16*>(base + off) = __float2bfloat16_rn(v);
        }
    } else {
        // --- producer half: stream X (b rows x i cols) ---
        const float* xc = x + (size_t)c * HW_;
        for (int idx = tid; idx < 16384; idx += 128) {
            int b = idx >> 7, i = idx & 127;
            float v = (i < 121) ? xc[(size_t)b * (C_*HW_) + i] : 0.0f;
            uint32_t off = 32768u + (uint32_t)b*256 + ((((uint32_t)i >> 3) ^ (b & 7)) << 4) + (i & 7)*2;
            *reinterpret_cast<__nv_bfloat16*>(base + off) = __float2bfloat16_rn(v);
        }
    }
    __syncthreads();

    // --- mma: warp tile 64(m=b) x 32(n=o); 8 k-steps of 16 ---
    int wm = (wid & 1) * 64, wn = (wid >> 1) * 32;
    float acc[4][4][4];
    #pragma unroll
    for (int mi = 0; mi < 4; mi++)
        #pragma unroll
        for (int ni = 0; ni < 4; ni++)
            #pragma unroll
            for (int e = 0; e < 4; e++) acc[mi][ni][e] = 0.0f;

    int a_row = ((lane >> 3) & 1) * 8 + (lane & 7);   // + wm + mi*16
    int a_kc  = (lane >> 4);                          // + k2*2
    int b_row = ((lane >> 4) << 3) + (lane & 7);      // + wn + np*16
    int b_kc  = ((lane >> 3) & 1);                    // + k2*2

    #pragma unroll 1
    for (int k2 = 0; k2 < 8; k2++) {
        uint32_t af[4][4], bf[2][4];
        #pragma unroll
        for (int mi = 0; mi < 4; mi++) {
            int row = wm + mi*16 + a_row;
            uint32_t addr = Xb + (uint32_t)row*256 + (((uint32_t)(k2*2 + a_kc) ^ (row & 7)) << 4);
            ldsm4(af[mi], addr);
        }
        #pragma unroll
        for (int np = 0; np < 2; np++) {
            int row = wn + np*16 + b_row;
            uint32_t addr = Tb + (uint32_t)row*256 + (((uint32_t)(k2*2 + b_kc) ^ (row & 7)) << 4);
            ldsm4(bf[np], addr);
        }
        #pragma unroll
        for (int mi = 0; mi < 4; mi++)
            #pragma unroll
            for (int ni = 0; ni < 4; ni++)
                mma16816(acc[mi][ni], af[mi],
                         bf[ni >> 1][(ni & 1) * 2], bf[ni >> 1][(ni & 1) * 2 + 1]);
    }
    __syncthreads();

    // --- stage D as bf16, pitch 264B (bank-spread), then coalesced copy-out ---
    {
        int r0 = lane >> 2, c0 = (lane & 3) * 2;
        #pragma unroll
        for (int mi = 0; mi < 4; mi++) {
            int brow = wm + mi*16 + r0;
            #pragma unroll
            for (int ni = 0; ni < 4; ni++) {
                int ocol = wn + ni*8 + c0;
                *reinterpret_cast<__nv_bfloat162*>(base + (size_t)brow*264 + ocol*2) =
                    __floats2bfloat162_rn(acc[mi][ni][0], acc[mi][ni][1]);
                *reinterpret_cast<__nv_bfloat162*>(base + (size_t)(brow+8)*264 + ocol*2) =
                    __floats2bfloat162_rn(acc[mi][ni][2], acc[mi][ni][3]);
            }
        }
    }
    __syncthreads();
    __nv_bfloat16* dst = g_xfb + (size_t)c * M_;
    for (int idx = tid; idx < M_; idx += 256) {
        int b = idx / 121, o = idx - b * 121;
        dst[idx] = *reinterpret_cast<__nv_bfloat16*>(base + (size_t)b*264 + o*2);
    }
}

// K2c: W fp32 -> bf16 (layout preserved, k contiguous).
__global__ __launch_bounds__(256)
void convert_w(const float4* __restrict__ w) {
    int i = blockIdx.x * 256 + threadIdx.x;
    float4 v = w[i];
    __nv_bfloat162* d2 = reinterpret_cast<__nv_bfloat162*>(g_wb);
    d2[2*i]   = __floats2bfloat162_rn(v.x, v.y);
    d2[2*i+1] = __floats2bfloat162_rn(v.z, v.w);
}

// ---------------------------------------------------------------------------
// K3: bf16 mma.sync GEMM. A = x_filt, COL-major [k][m], staged into 256B-row
// swizzled smem, consumed via ldmatrix.trans. B = W row-major [n][k], SW128.
// CTA 128x128, K-tile 64, 3-stage cp.async pipeline (ONE sync per iter,
// loads for t+2 issued before compute(t)). Fused BN/ReLU/gate/residual.
// ---------------------------------------------------------------------------
#define KT_    64
#define NKT_   (C_/KT_)          /* 32 */
#define ASTG   16384             /* 64 k-rows x 256B */
#define BSTG   16384             /* 128 n-rows x 128B */
#define STGSZ  (ASTG+BSTG)
#define SW(o)  ((o) ^ (((o) >> 3) & 0x70))

__global__ __launch_bounds__(256, 2)
void gemm_tc(const float* __restrict__ x,
             const float* __restrict__ cb, const float* __restrict__ ga,
             const float* __restrict__ be, const float* __restrict__ me,
             const float* __restrict__ va, const float* __restrict__ gate,
             float* __restrict__ out) {
    extern __shared__ char smc[];
    uint32_t sb    = smem_addr_u32(smc);
    uint32_t tiles = (sb + 1023) & ~1023u;

    int tid = threadIdx.x, wid = tid >> 5, lane = tid & 31;
    int bx = blockIdx.x, by = blockIdx.y;
    int wm = (wid & 1) * 64;
    int wn = (wid >> 1) * 32;

    const __nv_bfloat16* Ag = g_xfb + bx * 128;          // (k,m) at k*M_ + m
    const __nv_bfloat16* Bg = g_wb  + (size_t)(by * 128) * C_;

    auto load_stage = [&](int kt, int buf) {
        const __nv_bfloat16* as = Ag + (size_t)(kt * KT_) * M_;
        const __nv_bfloat16* bs = Bg + kt * KT_;
        uint32_t Ab = tiles + buf * STGSZ, Bb = Ab + ASTG;
        #pragma unroll
        for (int q = 0; q < 4; q++) {               // A: 64 k-rows x 16 chunks of 16B
            int idx = tid + q * 256;
            int row = idx >> 4, ch = idx & 15;
            cpa16(Ab + (uint32_t)row*256 + (((uint32_t)ch ^ (row & 7)) << 4),
                  as + (size_t)row * M_ + ch * 8);
        }
        #pragma unroll
        for (int q = 0; q < 4; q++) {               // B: 128 n-rows x 8 chunks of 16B
            int idx = tid + q * 256;
            int row = idx >> 3, ch = idx & 7;
            uint32_t off = row * 128 + ch * 16;
            cpa16(Bb + SW(off), bs + (size_t)row * C_ + ch * 8);
        }
    };

    float acc[4][4][4];
    #pragma unroll
    for (int mi = 0; mi < 4; mi++)
        #pragma unroll
        for (int ni = 0; ni < 4; ni++)
            #pragma unroll
            for (int e = 0; e < 4; e++) acc[mi][ni][e] = 0.0f;

    // A (trans): slot s=lane>>3: m_half=s&1, k_half=s>>1.
    int at_k  = ((lane >> 4) & 1) * 8 + (lane & 7);   // + ks*16  (k-row)
    int at_mh = ((lane >> 3) & 1) * 8;                // + wm + mi*16 (m elems)
    // B (non-trans), 128B rows:
    int b_row  = wn + ((lane >> 4) << 3) + (lane & 7);
    int b_colb = ((lane >> 3) & 1) * 16;

    load_stage(0, 0);
    asm volatile("cp.async.commit_group;" ::: "memory");
    load_stage(1, 1);
    asm volatile("cp.async.commit_group;" ::: "memory");

    int buf = 0, nbuf = 2;                               // compute buf, next-load buf
    #pragma unroll 1
    for (int t = 0; t < NKT_; t++) {
        asm volatile("cp.async.wait_group 1;" ::: "memory");   // stage t landed
        __syncthreads();

        if (t + 2 < NKT_) load_stage(t + 2, nbuf);
        asm volatile("cp.async.commit_group;" ::: "memory");

        uint32_t Ab = tiles + buf * STGSZ, Bb = Ab + ASTG;
        #pragma unroll
        for (int ks = 0; ks < 4; ks++) {
            uint32_t af[4][4], bf[2][4];
            int krow = ks * 16 + at_k;
            #pragma unroll
            for (int mi = 0; mi < 4; mi++) {
                int me = wm + mi*16 + at_mh;
                uint32_t addr = Ab + (uint32_t)krow*256 + ((((uint32_t)me >> 3) ^ (krow & 7)) << 4);
                ldsm4t(af[mi], addr);
            }
            #pragma unroll
            for (int np = 0; np < 2; np++) {
                uint32_t off = (uint32_t)(b_row + np*16) * 128 + ks*32 + b_colb;
                ldsm4(bf[np], Bb + SW(off));
            }
            #pragma unroll
            for (int mi = 0; mi < 4; mi++)
                #pragma unroll
                for (int ni = 0; ni < 4; ni++)
                    mma16816(acc[mi][ni], af[mi],
                             bf[ni >> 1][(ni & 1) * 2], bf[ni >> 1][(ni & 1) * 2 + 1]);
        }
        buf  = (buf  == 2) ? 0 : buf  + 1;
        nbuf = (nbuf == 2) ? 0 : nbuf + 1;
    }

    // Epilogue: smem col-major (pitch 132) + BN/ReLU/gate/residual.
    float* Ep   = reinterpret_cast<float*>(smc + (tiles - sb));
    float* s_sc = Ep + 132 * 128;
    float* s_bi = s_sc + 128;
    __syncthreads();
    {
        int r0 = lane >> 2, c0 = (lane & 3) * 2;
        #pragma unroll
        for (int mi = 0; mi < 4; mi++) {
            int mrow = wm + mi * 16 + r0;
            #pragma unroll
            for (int ni = 0; ni < 4; ni++) {
                int ncol = wn + ni * 8 + c0;
                Ep[(mrow)     + (ncol)     * 132] = acc[mi][ni][0];
                Ep[(mrow)     + (ncol + 1) * 132] = acc[mi][ni][1];
                Ep[(mrow + 8) + (ncol)     * 132] = acc[mi][ni][2];
                Ep[(mrow + 8) + (ncol + 1) * 132] = acc[mi][ni][3];
            }
        }
    }
    if (tid < 128) {
        int o = by * 128 + tid;
        float sc = ga[o] * rsqrtf(va[o] + 1e-5f);
        s_sc[tid] = sc;
        s_bi[tid] = (cb[o] - me[o]) * sc + be[o];
    }
    __syncthreads();

    float g = fminf(fmaxf(gate[0], 0.0f), 1.0f);
    #pragma unroll 4
    for (int q = 0; q < 64; q++) {
        int idx = tid + q * 256;
        int nn = idx >> 7, mm = idx & 127;
        float v = Ep[mm + nn * 132];
        v = fmaxf(v * s_sc[nn] + s_bi[nn], 0.0f);
        int m = bx * 128 + mm;
        int b = m / 121, hw = m - b * 121;
        size_t oi = (size_t)b * (C_*HW_) + (size_t)(by * 128 + nn) * HW_ + hw;
        out[oi] = x[oi] + g * v;
    }
}

// ---------------------------------------------------------------------------
extern "C" void kernel_launch(void* const* d_in, const int* in_sizes, int n_in,
                              void* d_out, int out_size) {
    const float* x    = (const float*)d_in[0];
    const float* ft   = (const float*)d_in[1];
    const float* gate = (const float*)d_in[2];
    const float* w    = (const float*)d_in[3];
    const float* cbias= (const float*)d_in[4];
    const float* ga   = (const float*)d_in[5];
    const float* be   = (const float*)d_in[6];
    const float* me   = (const float*)d_in[7];
    const float* va   = (const float*)d_in[8];
    float* out = (float*)d_out;

    size_t smemF = 2048 + 2 * 32768;                 // hdr + T + X
    cudaFuncSetAttribute(filter_mma2, cudaFuncAttributeMaxDynamicSharedMemorySize, (int)smemF);
    filter_mma2<<<C_, 256, smemF>>>(x, ft);

    convert_w<<<(C_*C_/4)/256, 256>>>((const float4*)w);

    size_t stages = 1024 + 3 * STGSZ;                // ~97 KB (3-stage)
    size_t epi    = 1024 + (132*128 + 256) * sizeof(float);
    size_t smem3  = stages > epi ? stages : epi;
    cudaFuncSetAttribute(gemm_tc, cudaFuncAttributeMaxDynamicSharedMemorySize, (int)smem3);
    gemm_tc<<<dim3(121, 16), 256, smem3>>>(x, cbias, ga, be, me, va, gate, out);
}